// round 6
// baseline (speedup 1.0000x reference)
#include <cuda_runtime.h>

// Problem constants
#define N_   5000
#define D_   128
#define T_   100
#define K_   20
#define EPSV 1e-8f

// Tile config: block covers NT x DT x TC of (n, d, t)
#define NT 32
#define DT 32
#define TC 32
#define NTHREADS 512

// dynamic smem: s_theta[K][NT][TC] + s_phi2[K][DT/2][TC](float2) + s_evt[NT][DT](int)
#define SMEM_FLOATS (K_*NT*TC /*theta*/ + K_*(DT/2)*TC*2 /*phi2*/ + NT*DT /*evt*/)
#define SMEM_BYTES  (SMEM_FLOATS * 4)

// Fallback scratch for phi_prob if the harness's out buffer doesn't include it.
__device__ float g_phip_scratch[K_ * D_ * T_];

// ---------------------------------------------------------------------------
// Kernel 1: phi_prob = sigmoid(phi)   (256,000 elems -> d_out phi region)
// ---------------------------------------------------------------------------
__global__ void sigmoid_kernel(const float4* __restrict__ phi,
                               float4* __restrict__ out) {
    int i = blockIdx.x * blockDim.x + threadIdx.x;
    if (i < (K_ * D_ * T_) / 4) {
        float4 v = phi[i];
        v.x = __fdividef(1.0f, 1.0f + __expf(-v.x));
        v.y = __fdividef(1.0f, 1.0f + __expf(-v.y));
        v.z = __fdividef(1.0f, 1.0f + __expf(-v.z));
        v.w = __fdividef(1.0f, 1.0f + __expf(-v.w));
        out[i] = v;
    }
}

// ---------------------------------------------------------------------------
// Kernel 2: fused softmax(K) + mixture GEMM + mask + clip
//   grid: (ceil(N/NT), D/DT, ceil(T/TC)), block: 512 threads (16 warps)
//   warp lanes map to t (coalesced smem + coalesced 128B pi stores)
//   per-warp tile: 8 n x 8 d (4 f32x2 d-pairs), per-thread 32 f32x2 accs
// ---------------------------------------------------------------------------
__global__ __launch_bounds__(NTHREADS, 1)
void aladyn_main_kernel(const float* __restrict__ lam,
                        const float* __restrict__ phip,
                        const int*   __restrict__ evt,   // int32 (JAX x64 off)
                        float*       __restrict__ pi,
                        float*       __restrict__ theta_out,
                        int                       write_theta) {
    extern __shared__ float smem[];
    float*  s_th = smem;                                  // [K][NT][TC]
    float2* s_ph = (float2*)(smem + K_ * NT * TC);        // [K][DT/2][TC]
    int*    s_ev = (int*)(smem + 2 * K_ * NT * TC);       // [NT][DT]

    const int tid = threadIdx.x;
    const int n0 = blockIdx.x * NT;
    const int d0 = blockIdx.y * DT;
    const int t0 = blockIdx.z * TC;

    // ---- fill lambda tile -> s_th (gmem coalesced: t fastest, 128B runs) ----
    for (int f = tid; f < NT * K_ * TC; f += NTHREADS) {
        int j = f & 31;
        int k = (f >> 5) % K_;
        int i = f / (K_ * 32);
        int n = n0 + i, t = t0 + j;
        float v = 0.0f;
        if (n < N_ && t < T_) v = lam[n * (K_ * T_) + k * T_ + t];
        s_th[(k * NT + i) * TC + j] = v;
    }
    // ---- fill phi_prob tile as d-paired float2 ----
    for (int f = tid; f < K_ * (DT / 2) * TC; f += NTHREADS) {
        int j  = f & 31;
        int dp = (f >> 5) & ((DT / 2) - 1);
        int k  = f / ((DT / 2) * 32);
        int t  = t0 + j;
        float2 v = make_float2(0.0f, 0.0f);
        if (t < T_) {
            int base = k * (D_ * T_) + (d0 + 2 * dp) * T_ + t;
            v.x = phip[base];
            v.y = phip[base + T_];
        }
        s_ph[(k * (DT / 2) + dp) * TC + j] = v;
    }
    // ---- fill event-time tile (int32) ----
    for (int f = tid; f < NT * DT; f += NTHREADS) {
        int c = f & (DT - 1);
        int i = f / DT;
        int n = n0 + i;
        int e = 0;
        if (n < N_) e = evt[(size_t)n * D_ + d0 + c];
        s_ev[f] = e;
    }
    __syncthreads();

    // ---- softmax over K in place (per (n,t) column) ----
    for (int p = tid; p < NT * TC; p += NTHREADS) {
        int j = p & 31;
        int i = p >> 5;
        float* col = &s_th[i * TC + j];  // stride NT*TC between k
        float m = col[0];
        #pragma unroll
        for (int k = 1; k < K_; ++k) m = fmaxf(m, col[k * NT * TC]);
        float e[K_];
        float s = 0.0f;
        #pragma unroll
        for (int k = 0; k < K_; ++k) {
            e[k] = __expf(col[k * NT * TC] - m);
            s += e[k];
        }
        float inv = __fdividef(1.0f, s);
        #pragma unroll
        for (int k = 0; k < K_; ++k) col[k * NT * TC] = e[k] * inv;
    }
    __syncthreads();

    // ---- theta output (only one d-tile writes it; partition is exact) ----
    if (write_theta && blockIdx.y == 0) {
        for (int f = tid; f < NT * K_ * TC; f += NTHREADS) {
            int j = f & 31;
            int k = (f >> 5) % K_;
            int i = f / (K_ * 32);
            int n = n0 + i, t = t0 + j;
            if (n < N_ && t < T_)
                theta_out[n * (K_ * T_) + k * T_ + t] = s_th[(k * NT + i) * TC + j];
        }
    }

    // ---- GEMM: pi[n,d,t] = sum_k theta * phi_prob, f32x2 over d-pairs ----
    const int w    = tid >> 5;
    const int lane = tid & 31;         // lane == t index within chunk
    const int wn   = w >> 2;           // 0..3
    const int wd   = w & 3;            // 0..3
    const int nb   = wn * 8;           // local n base (8 rows)
    const int dpb  = wd * 4;           // local d-pair base (4 pairs = 8 d)

    unsigned long long acc[8][4];
    #pragma unroll
    for (int i = 0; i < 8; ++i)
        #pragma unroll
        for (int p = 0; p < 4; ++p) acc[i][p] = 0ULL;

    #pragma unroll
    for (int k = 0; k < K_; ++k) {
        unsigned long long a2[8];
        const float* th = &s_th[(k * NT + nb) * TC + lane];
        #pragma unroll
        for (int i = 0; i < 8; ++i) {
            float a = th[i * TC];
            asm("mov.b64 %0, {%1, %1};" : "=l"(a2[i]) : "f"(a));
        }
        unsigned long long b2[4];
        const float2* ph = &s_ph[(k * (DT / 2) + dpb) * TC + lane];
        #pragma unroll
        for (int p = 0; p < 4; ++p)
            b2[p] = *reinterpret_cast<const unsigned long long*>(&ph[p * TC]);
        #pragma unroll
        for (int i = 0; i < 8; ++i)
            #pragma unroll
            for (int p = 0; p < 4; ++p)
                asm("fma.rn.f32x2 %0, %1, %2, %0;"
                    : "+l"(acc[i][p]) : "l"(a2[i]), "l"(b2[p]));
    }

    // ---- epilogue: mask (t <= event_time), clip, coalesced stores ----
    const int t  = t0 + lane;
    const bool tv = (t < T_);
    #pragma unroll
    for (int i = 0; i < 8; ++i) {
        int n = n0 + nb + i;
        if (n >= N_) break;  // warp-uniform
        float* prow = pi + (size_t)n * (D_ * T_);
        #pragma unroll
        for (int p = 0; p < 4; ++p) {
            float v0, v1;
            asm("mov.b64 {%0, %1}, %2;" : "=f"(v0), "=f"(v1) : "l"(acc[i][p]));
            int c  = (dpb + p) * 2;
            int e0 = s_ev[(nb + i) * DT + c];
            int e1 = s_ev[(nb + i) * DT + c + 1];
            v0 = (t <= e0) ? v0 : 0.0f;
            v1 = (t <= e1) ? v1 : 0.0f;
            v0 = fminf(fmaxf(v0, EPSV), 1.0f - EPSV);
            v1 = fminf(fmaxf(v1, EPSV), 1.0f - EPSV);
            if (tv) {
                prow[(d0 + c) * T_ + t]     = v0;  // warp: 128B contiguous
                prow[(d0 + c + 1) * T_ + t] = v1;
            }
        }
    }
}

// ---------------------------------------------------------------------------
// Launch
// ---------------------------------------------------------------------------
extern "C" void kernel_launch(void* const* d_in, const int* in_sizes, int n_in,
                              void* d_out, int out_size) {
    const float* lam = (const float*)d_in[0];  // [N,K,T] f32
    const float* phi = (const float*)d_in[1];  // [K,D,T] f32
    const int*   evt = (const int*)d_in[2];    // [N,D]   i32 (JAX x64 off)

    const long long PI_SZ  = (long long)N_ * D_ * T_;  // 64,000,000
    const long long TH_SZ  = (long long)N_ * K_ * T_;  // 10,000,000
    const long long PHP_SZ = (long long)K_ * D_ * T_;  //    256,000

    float* out   = (float*)d_out;
    float* pi    = out;                         // [N,D,T]
    float* theta = out + PI_SZ;                 // [N,K,T]
    float* phip  = out + PI_SZ + TH_SZ;         // [K,D,T]

    // Guard against a different output packing: never write past out_size.
    const long long osz = (long long)out_size;
    const int has_theta = (osz >= PI_SZ + TH_SZ);
    const int has_phip  = (osz >= PI_SZ + TH_SZ + PHP_SZ);

    // phi_prob = sigmoid(phi), computed once
    int nvec = (K_ * D_ * T_) / 4;  // 64000
    if (has_phip) {
        sigmoid_kernel<<<(nvec + 255) / 256, 256>>>((const float4*)phi,
                                                    (float4*)phip);
    } else {
        float* ps;
        cudaGetSymbolAddress((void**)&ps, g_phip_scratch);
        sigmoid_kernel<<<(nvec + 255) / 256, 256>>>((const float4*)phi,
                                                    (float4*)ps);
        phip = ps;
    }

    cudaFuncSetAttribute(aladyn_main_kernel,
                         cudaFuncAttributeMaxDynamicSharedMemorySize, SMEM_BYTES);
    dim3 grid((N_ + NT - 1) / NT, D_ / DT, (T_ + TC - 1) / TC);  // 157 x 4 x 4
    aladyn_main_kernel<<<grid, NTHREADS, SMEM_BYTES>>>(lam, phip, evt, pi, theta,
                                                       has_theta);
}